// round 8
// baseline (speedup 1.0000x reference)
#include <cuda_runtime.h>
#include <cuda_bf16.h>
#include <cstdint>

// out[b,i,:] = sum_j exp(q_i . k_j) * v_j   (B=4, S=4096, D=64, fp32)
// mma.sync bf16 split-precision, FA-style register P.
// R8: term-major MMA ordering (8-deep independent accumulator chains) +
//     double-buffered K/V with ONE __syncthreads per tile.

#define S_LEN 4096
#define B_SZ  4
#define DD    64
#define TQ    128
#define TK    128
#define NTH   256
#define NTILES (S_LEN / TK)

#define PITCH 144              // 64 bf16 + 8B pad
#define QB    (TK * PITCH)     // 18432 per hi/lo buffer

// K: buf0 hi@0 lo@QB, buf1 hi@2QB lo@3QB.  V: same at SM_V.
#define SM_K  0
#define SM_V  (4 * QB)
#define SM_TOTAL (8 * QB)      // 147456 B

#define LOG2E 1.4426950408889634f

__device__ __forceinline__ uint32_t smem_u32(const void* p) {
    uint32_t a;
    asm("{ .reg .u64 t; cvta.to.shared.u64 t, %1; cvt.u32.u64 %0, t; }" : "=r"(a) : "l"(p));
    return a;
}
#define LDMX4(r, a) \
    asm volatile("ldmatrix.sync.aligned.m8n8.x4.shared.b16 {%0,%1,%2,%3}, [%4];" \
        : "=r"((r)[0]), "=r"((r)[1]), "=r"((r)[2]), "=r"((r)[3]) : "r"(a))
#define LDMX4T(r, a) \
    asm volatile("ldmatrix.sync.aligned.m8n8.x4.trans.shared.b16 {%0,%1,%2,%3}, [%4];" \
        : "=r"((r)[0]), "=r"((r)[1]), "=r"((r)[2]), "=r"((r)[3]) : "r"(a))
#define MMA(c, av, bv) \
    asm volatile("mma.sync.aligned.m16n8k16.row.col.f32.bf16.bf16.f32 " \
        "{%0,%1,%2,%3}, {%4,%5,%6,%7}, {%8,%9}, {%0,%1,%2,%3};" \
        : "+f"((c)[0]), "+f"((c)[1]), "+f"((c)[2]), "+f"((c)[3]) \
        : "r"((av)[0]), "r"((av)[1]), "r"((av)[2]), "r"((av)[3]), \
          "r"((bv)[0]), "r"((bv)[1]))

__device__ __forceinline__ float ex2f(float x) {
    float r;
    asm("ex2.approx.ftz.f32 %0, %1;" : "=f"(r) : "f"(x));
    return r;
}
__device__ __forceinline__ void split_pack(float x, float y, uint32_t& hi, uint32_t& lo) {
    __nv_bfloat16 xh = __float2bfloat16(x), yh = __float2bfloat16(y);
    float xr = x - __bfloat162float(xh);
    float yr = y - __bfloat162float(yh);
    __nv_bfloat16 xl = __float2bfloat16(xr), yl = __float2bfloat16(yr);
    hi = ((uint32_t)__bfloat16_as_ushort(yh) << 16) | (uint32_t)__bfloat16_as_ushort(xh);
    lo = ((uint32_t)__bfloat16_as_ushort(yl) << 16) | (uint32_t)__bfloat16_as_ushort(xl);
}
__device__ __forceinline__ void ldg_tile(const float* __restrict__ g, float4 r[8], int tid) {
    #pragma unroll
    for (int i = 0; i < 8; ++i) {
        int f = tid + i * NTH;
        int row = f >> 4, d0 = (f & 15) << 2;
        r[i] = *(const float4*)&g[(size_t)row * DD + d0];
    }
}
__device__ __forceinline__ void sts_tile(const float4 r[8], char* smhi, int tid, float scale) {
    #pragma unroll
    for (int i = 0; i < 8; ++i) {
        int f = tid + i * NTH;
        int row = f >> 4, d0 = (f & 15) << 2;
        uint32_t h0, l0, h1, l1;
        split_pack(r[i].x * scale, r[i].y * scale, h0, l0);
        split_pack(r[i].z * scale, r[i].w * scale, h1, l1);
        int off = row * PITCH + d0 * 2;
        *(uint2*)(smhi + off)      = make_uint2(h0, h1);
        *(uint2*)(smhi + QB + off) = make_uint2(l0, l1);
    }
}

__global__ void __launch_bounds__(NTH, 1)
fa_fa8_kernel(const float* __restrict__ q, const float* __restrict__ k,
              const float* __restrict__ v, float* __restrict__ out)
{
    extern __shared__ char smem[];
    const uint32_t sb = smem_u32(smem);
    const int tid  = threadIdx.x;
    const int wid  = tid >> 5;
    const int lane = tid & 31;
    const int b  = blockIdx.y;
    const int q0 = blockIdx.x * TQ;

    const float* Qg = q + ((size_t)b * S_LEN + q0) * DD;
    const float* Kg = k + (size_t)b * S_LEN * DD;
    const float* Vg = v + (size_t)b * S_LEN * DD;
    float*       Og = out + ((size_t)b * S_LEN + q0) * DD;

    // ---- prologue: stage Q (x log2e) through K buf0, grab persistent A-frags ----
    float4 pf[8];
    ldg_tile(Qg, pf, tid);
    sts_tile(pf, smem + SM_K, tid, LOG2E);
    __syncthreads();

    uint32_t qhi[4][4], qlo[4][4];
    {
        const uint32_t aQ = sb + SM_K +
            (uint32_t)((wid * 16 + (lane & 15)) * PITCH + (lane >> 4) * 16);
        #pragma unroll
        for (int ks = 0; ks < 4; ++ks) {
            LDMX4(qhi[ks], aQ + ks * 32);
            LDMX4(qlo[ks], aQ + QB + ks * 32);
        }
    }
    __syncthreads();

    // stage K0, V0 into buf0
    ldg_tile(Kg, pf, tid);
    sts_tile(pf, smem + SM_K, tid, 1.0f);
    ldg_tile(Vg, pf, tid);
    sts_tile(pf, smem + SM_V, tid, 1.0f);
    __syncthreads();

    // per-lane B-operand ldmatrix bases (buf0; add cur for buf1)
    const uint32_t bK = sb + SM_K +
        (uint32_t)(( ((lane >> 4) & 1) * 8 + (lane & 7) ) * PITCH + ((lane >> 3) & 1) * 16);
    const uint32_t bV = sb + SM_V +
        (uint32_t)(( ((lane >> 3) & 1) * 8 + (lane & 7) ) * PITCH + (((lane >> 4) & 1) * 8) * 2);

    float acc2[8][4];
    #pragma unroll
    for (int ni = 0; ni < 8; ++ni)
        #pragma unroll
        for (int e = 0; e < 4; ++e) acc2[ni][e] = 0.0f;

    for (int t = 0; t < NTILES; ++t) {
        const int tn = (t + 1 < NTILES) ? t + 1 : 0;     // clamped prefetch
        const uint32_t cur = (uint32_t)((t & 1) * 2 * QB);
        const uint32_t nxt = (uint32_t)(((t + 1) & 1) * 2 * QB);

        // ---- prefetch K(t+1); GEMM1(t): S(16 x 128 per warp) ----
        ldg_tile(Kg + (size_t)(tn * TK) * DD, pf, tid);

        float acc1[16][4];
        #pragma unroll
        for (int n = 0; n < 16; ++n)
            #pragma unroll
            for (int e = 0; e < 4; ++e) acc1[n][e] = 0.0f;

        #pragma unroll
        for (int ks = 0; ks < 4; ++ks) {
            #pragma unroll
            for (int g4 = 0; g4 < 2; ++g4) {       // groups of 4 n-pairs
                uint32_t bh[4][4], bl[4][4];
                #pragma unroll
                for (int p = 0; p < 4; ++p) {
                    uint32_t bb = bK + cur +
                        (uint32_t)(((g4 * 4 + p) * 16) * PITCH + ks * 32);
                    LDMX4(bh[p], bb);
                    LDMX4(bl[p], bb + QB);
                }
                // term-major: 8 independent chains per term pass
                #pragma unroll
                for (int p = 0; p < 4; ++p) {
                    int n = (g4 * 4 + p) * 2;
                    MMA(acc1[n],     qhi[ks], bh[p]);
                    MMA(acc1[n + 1], qhi[ks], bh[p] + 2);
                }
                #pragma unroll
                for (int p = 0; p < 4; ++p) {
                    int n = (g4 * 4 + p) * 2;
                    MMA(acc1[n],     qhi[ks], bl[p]);
                    MMA(acc1[n + 1], qhi[ks], bl[p] + 2);
                }
                #pragma unroll
                for (int p = 0; p < 4; ++p) {
                    int n = (g4 * 4 + p) * 2;
                    MMA(acc1[n],     qlo[ks], bh[p]);
                    MMA(acc1[n + 1], qlo[ks], bh[p] + 2);
                }
            }
        }

        // K(t+1) -> other buffer (no reader there this tile); V(t+1) prefetch
        sts_tile(pf, smem + SM_K + nxt, tid, 1.0f);
        ldg_tile(Vg + (size_t)(tn * TK) * DD, pf, tid);

        // ---- GEMM2(t): O += P @ V, exp+split fused, term-major ----
        #pragma unroll
        for (int ks = 0; ks < 8; ++ks) {
            uint32_t phi[4], plo[4];
            {
                float e0 = ex2f(acc1[2*ks][0]);
                float e1 = ex2f(acc1[2*ks][1]);
                float e2 = ex2f(acc1[2*ks][2]);
                float e3 = ex2f(acc1[2*ks][3]);
                split_pack(e0, e1, phi[0], plo[0]);
                split_pack(e2, e3, phi[1], plo[1]);
                float f0 = ex2f(acc1[2*ks+1][0]);
                float f1 = ex2f(acc1[2*ks+1][1]);
                float f2 = ex2f(acc1[2*ks+1][2]);
                float f3 = ex2f(acc1[2*ks+1][3]);
                split_pack(f0, f1, phi[2], plo[2]);
                split_pack(f2, f3, phi[3], plo[3]);
            }
            uint32_t bh[4][4], bl[4][4];
            #pragma unroll
            for (int p = 0; p < 4; ++p) {
                uint32_t bb = bV + cur + (uint32_t)(ks * 16 * PITCH + p * 32);
                LDMX4T(bh[p], bb);
                LDMX4T(bl[p], bb + QB);
            }
            #pragma unroll
            for (int p = 0; p < 4; ++p) {
                MMA(acc2[2*p],     phi, bh[p]);
                MMA(acc2[2*p + 1], phi, bh[p] + 2);
            }
            #pragma unroll
            for (int p = 0; p < 4; ++p) {
                MMA(acc2[2*p],     phi, bl[p]);
                MMA(acc2[2*p + 1], phi, bl[p] + 2);
            }
            #pragma unroll
            for (int p = 0; p < 4; ++p) {
                MMA(acc2[2*p],     plo, bh[p]);
                MMA(acc2[2*p + 1], plo, bh[p] + 2);
            }
        }

        sts_tile(pf, smem + SM_V + nxt, tid, 1.0f);  // V(t+1)
        __syncthreads();   // single barrier: t+1 buffers visible; cur reads done
    }

    // ---- epilogue: O rows wid*16 .. +16 ----
    #pragma unroll
    for (int ni = 0; ni < 8; ++ni) {
        int r = wid * 16 + (lane >> 2);
        int c = ni * 8 + (lane & 3) * 2;
        *(float2*)&Og[(size_t)r * DD + c]       = make_float2(acc2[ni][0], acc2[ni][1]);
        *(float2*)&Og[(size_t)(r + 8) * DD + c] = make_float2(acc2[ni][2], acc2[ni][3]);
    }
}

extern "C" void kernel_launch(void* const* d_in, const int* in_sizes, int n_in,
                              void* d_out, int out_size)
{
    const float* q = (const float*)d_in[0];
    const float* k = (const float*)d_in[1];
    const float* v = (const float*)d_in[2];
    float* out = (float*)d_out;
    (void)in_sizes; (void)n_in; (void)out_size;

    cudaFuncSetAttribute(fa_fa8_kernel,
                         cudaFuncAttributeMaxDynamicSharedMemorySize, SM_TOTAL);
    dim3 grid(S_LEN / TQ, B_SZ);   // 32 x 4 = 128 CTAs, one wave
    fa_fa8_kernel<<<grid, NTH, SM_TOTAL>>>(q, k, v, out);
}

// round 9
// speedup vs baseline: 1.0610x; 1.0610x over previous
#include <cuda_runtime.h>
#include <cuda_bf16.h>
#include <cstdint>

// out[b,i,:] = sum_j exp(q_i . k_j) * v_j   (B=4, S=4096, D=64, fp32)
// mma.sync bf16 split-precision, FA-style register P.
// R9: TK=64 half-tiles -> acc1/prefetch register footprint halved (no spills).

#define S_LEN 4096
#define B_SZ  4
#define DD    64
#define TQ    128
#define TK    64
#define NTH   256
#define NTILES (S_LEN / TK)

#define PITCH 144              // 64 bf16 + 8B pad
#define KBUF  (TK * PITCH)     // 9216 per hi/lo buffer

#define SM_K  0                // K hi @0, lo @KBUF
#define SM_V  (2 * KBUF)       // V hi, lo
#define SM_TOTAL (4 * KBUF)    // 36864 B

#define LOG2E 1.4426950408889634f

__device__ __forceinline__ uint32_t smem_u32(const void* p) {
    uint32_t a;
    asm("{ .reg .u64 t; cvta.to.shared.u64 t, %1; cvt.u32.u64 %0, t; }" : "=r"(a) : "l"(p));
    return a;
}
#define LDMX4(r, a) \
    asm volatile("ldmatrix.sync.aligned.m8n8.x4.shared.b16 {%0,%1,%2,%3}, [%4];" \
        : "=r"((r)[0]), "=r"((r)[1]), "=r"((r)[2]), "=r"((r)[3]) : "r"(a))
#define LDMX4T(r, a) \
    asm volatile("ldmatrix.sync.aligned.m8n8.x4.trans.shared.b16 {%0,%1,%2,%3}, [%4];" \
        : "=r"((r)[0]), "=r"((r)[1]), "=r"((r)[2]), "=r"((r)[3]) : "r"(a))
#define MMA(c, av, bv) \
    asm volatile("mma.sync.aligned.m16n8k16.row.col.f32.bf16.bf16.f32 " \
        "{%0,%1,%2,%3}, {%4,%5,%6,%7}, {%8,%9}, {%0,%1,%2,%3};" \
        : "+f"((c)[0]), "+f"((c)[1]), "+f"((c)[2]), "+f"((c)[3]) \
        : "r"((av)[0]), "r"((av)[1]), "r"((av)[2]), "r"((av)[3]), \
          "r"((bv)[0]), "r"((bv)[1]))

__device__ __forceinline__ float ex2f(float x) {
    float r;
    asm("ex2.approx.ftz.f32 %0, %1;" : "=f"(r) : "f"(x));
    return r;
}
__device__ __forceinline__ void split_pack(float x, float y, uint32_t& hi, uint32_t& lo) {
    __nv_bfloat16 xh = __float2bfloat16(x), yh = __float2bfloat16(y);
    float xr = x - __bfloat162float(xh);
    float yr = y - __bfloat162float(yh);
    __nv_bfloat16 xl = __float2bfloat16(xr), yl = __float2bfloat16(yr);
    hi = ((uint32_t)__bfloat16_as_ushort(yh) << 16) | (uint32_t)__bfloat16_as_ushort(xh);
    lo = ((uint32_t)__bfloat16_as_ushort(yl) << 16) | (uint32_t)__bfloat16_as_ushort(xl);
}
// LDG a [ROWS x 64] fp32 tile (ROWS*16/NTH float4 per thread)
template<int ROWS>
__device__ __forceinline__ void ldg_tile(const float* __restrict__ g,
                                         float4* r, int tid) {
    #pragma unroll
    for (int i = 0; i < (ROWS * 16) / NTH; ++i) {
        int f = tid + i * NTH;
        int row = f >> 4, d0 = (f & 15) << 2;
        r[i] = *(const float4*)&g[(size_t)row * DD + d0];
    }
}
template<int ROWS>
__device__ __forceinline__ void sts_tile(const float4* r, char* smhi, int bufsz,
                                         int tid, float scale) {
    #pragma unroll
    for (int i = 0; i < (ROWS * 16) / NTH; ++i) {
        int f = tid + i * NTH;
        int row = f >> 4, d0 = (f & 15) << 2;
        uint32_t h0, l0, h1, l1;
        split_pack(r[i].x * scale, r[i].y * scale, h0, l0);
        split_pack(r[i].z * scale, r[i].w * scale, h1, l1);
        int off = row * PITCH + d0 * 2;
        *(uint2*)(smhi + off)         = make_uint2(h0, h1);
        *(uint2*)(smhi + bufsz + off) = make_uint2(l0, l1);
    }
}

__global__ void __launch_bounds__(NTH, 1)
fa_fa9_kernel(const float* __restrict__ q, const float* __restrict__ k,
              const float* __restrict__ v, float* __restrict__ out)
{
    extern __shared__ char smem[];
    const uint32_t sb = smem_u32(smem);
    const int tid  = threadIdx.x;
    const int wid  = tid >> 5;
    const int lane = tid & 31;
    const int b  = blockIdx.y;
    const int q0 = blockIdx.x * TQ;

    const float* Qg = q + ((size_t)b * S_LEN + q0) * DD;
    const float* Kg = k + (size_t)b * S_LEN * DD;
    const float* Vg = v + (size_t)b * S_LEN * DD;
    float*       Og = out + ((size_t)b * S_LEN + q0) * DD;

    // ---- prologue: stage Q (x log2e) across whole smem (K+V regions), grab A-frags ----
    {
        float4 qf[8];
        ldg_tile<TQ>(Qg, qf, tid);
        sts_tile<TQ>(qf, smem, TQ * PITCH, tid, LOG2E);  // hi @0 (18432), lo @18432
    }
    __syncthreads();

    uint32_t qhi[4][4], qlo[4][4];
    {
        const uint32_t aQ = sb +
            (uint32_t)((wid * 16 + (lane & 15)) * PITCH + (lane >> 4) * 16);
        #pragma unroll
        for (int ks = 0; ks < 4; ++ks) {
            LDMX4(qhi[ks], aQ + ks * 32);
            LDMX4(qlo[ks], aQ + TQ * PITCH + ks * 32);
        }
    }
    __syncthreads();

    // stage K0, V0
    float4 pf[4];
    ldg_tile<TK>(Kg, pf, tid);
    sts_tile<TK>(pf, smem + SM_K, KBUF, tid, 1.0f);
    ldg_tile<TK>(Vg, pf, tid);
    sts_tile<TK>(pf, smem + SM_V, KBUF, tid, 1.0f);
    __syncthreads();

    // per-lane B-operand ldmatrix bases
    const uint32_t bK = sb + SM_K +
        (uint32_t)(( ((lane >> 4) & 1) * 8 + (lane & 7) ) * PITCH + ((lane >> 3) & 1) * 16);
    const uint32_t bV = sb + SM_V +
        (uint32_t)(( ((lane >> 3) & 1) * 8 + (lane & 7) ) * PITCH + (((lane >> 4) & 1) * 8) * 2);

    float acc2[8][4];
    #pragma unroll
    for (int ni = 0; ni < 8; ++ni)
        #pragma unroll
        for (int e = 0; e < 4; ++e) acc2[ni][e] = 0.0f;

    for (int t = 0; t < NTILES; ++t) {
        const int tn = (t + 1 < NTILES) ? t + 1 : 0;

        // ---- prefetch K(t+1); GEMM1(t): S(16 x 64 per warp) ----
        ldg_tile<TK>(Kg + (size_t)(tn * TK) * DD, pf, tid);

        float acc1[8][4];
        #pragma unroll
        for (int n = 0; n < 8; ++n)
            #pragma unroll
            for (int e = 0; e < 4; ++e) acc1[n][e] = 0.0f;

        #pragma unroll
        for (int ks = 0; ks < 4; ++ks) {
            #pragma unroll
            for (int p = 0; p < 4; ++p) {     // n-pairs: blocks 2p, 2p+1 (64 keys)
                uint32_t bb = bK + (uint32_t)(p * 16 * PITCH + ks * 32);
                uint32_t bhi[4], blo[4];
                LDMX4(bhi, bb);
                LDMX4(blo, bb + KBUF);
                MMA(acc1[2*p],   qhi[ks], bhi);
                MMA(acc1[2*p],   qhi[ks], blo);
                MMA(acc1[2*p],   qlo[ks], bhi);
                MMA(acc1[2*p+1], qhi[ks], bhi + 2);
                MMA(acc1[2*p+1], qhi[ks], blo + 2);
                MMA(acc1[2*p+1], qlo[ks], bhi + 2);
            }
        }
        __syncthreads();                      // all warps done reading K(t)

        sts_tile<TK>(pf, smem + SM_K, KBUF, tid, 1.0f);   // K(t+1)
        ldg_tile<TK>(Vg + (size_t)(tn * TK) * DD, pf, tid);

        // ---- GEMM2(t): O += P @ V, exp+split fused per 16-key step ----
        #pragma unroll
        for (int ks = 0; ks < 4; ++ks) {
            uint32_t phi[4], plo[4];
            {
                float e0 = ex2f(acc1[2*ks][0]);
                float e1 = ex2f(acc1[2*ks][1]);
                float e2 = ex2f(acc1[2*ks][2]);
                float e3 = ex2f(acc1[2*ks][3]);
                split_pack(e0, e1, phi[0], plo[0]);
                split_pack(e2, e3, phi[1], plo[1]);
                float f0 = ex2f(acc1[2*ks+1][0]);
                float f1 = ex2f(acc1[2*ks+1][1]);
                float f2 = ex2f(acc1[2*ks+1][2]);
                float f3 = ex2f(acc1[2*ks+1][3]);
                split_pack(f0, f1, phi[2], plo[2]);
                split_pack(f2, f3, phi[3], plo[3]);
            }
            #pragma unroll
            for (int p = 0; p < 4; ++p) {     // d-pairs: blocks 2p, 2p+1
                uint32_t bb = bV + (uint32_t)(ks * 16 * PITCH + p * 32);
                uint32_t bhi[4], blo[4];
                LDMX4T(bhi, bb);
                LDMX4T(blo, bb + KBUF);
                MMA(acc2[2*p],   phi, bhi);
                MMA(acc2[2*p],   phi, blo);
                MMA(acc2[2*p],   plo, bhi);
                MMA(acc2[2*p+1], phi, bhi + 2);
                MMA(acc2[2*p+1], phi, blo + 2);
                MMA(acc2[2*p+1], plo, bhi + 2);
            }
        }
        __syncthreads();                      // all warps done reading V(t)
        sts_tile<TK>(pf, smem + SM_V, KBUF, tid, 1.0f);   // V(t+1)
    }

    // ---- epilogue: O rows wid*16 .. +16 ----
    #pragma unroll
    for (int ni = 0; ni < 8; ++ni) {
        int r = wid * 16 + (lane >> 2);
        int c = ni * 8 + (lane & 3) * 2;
        *(float2*)&Og[(size_t)r * DD + c]       = make_float2(acc2[ni][0], acc2[ni][1]);
        *(float2*)&Og[(size_t)(r + 8) * DD + c] = make_float2(acc2[ni][2], acc2[ni][3]);
    }
}

extern "C" void kernel_launch(void* const* d_in, const int* in_sizes, int n_in,
                              void* d_out, int out_size)
{
    const float* q = (const float*)d_in[0];
    const float* k = (const float*)d_in[1];
    const float* v = (const float*)d_in[2];
    float* out = (float*)d_out;
    (void)in_sizes; (void)n_in; (void)out_size;

    cudaFuncSetAttribute(fa_fa9_kernel,
                         cudaFuncAttributeMaxDynamicSharedMemorySize, SM_TOTAL);
    dim3 grid(S_LEN / TQ, B_SZ);   // 32 x 4 = 128 CTAs, one wave
    fa_fa9_kernel<<<grid, NTH, SM_TOTAL>>>(q, k, v, out);
}

// round 10
// speedup vs baseline: 1.0803x; 1.0182x over previous
#include <cuda_runtime.h>
#include <cuda_bf16.h>
#include <cstdint>

// out[b,i,:] = sum_j exp(q_i . k_j) * v_j   (B=4, S=4096, D=64, fp32)
// mma.sync bf16 split-precision, FA-style register P.
// R10: 512 threads (16 warps, 4/SMSP) split 8M x 2K; GEMM2 split-K over
//      key halves, one cross-warp reduction at the end. <=128 regs/thread.

#define S_LEN 4096
#define B_SZ  4
#define DD    64
#define TQ    128
#define TK    64
#define NTH   512
#define NTILES (S_LEN / TK)

#define PITCH 144              // 64 bf16 + 8B pad
#define KBUF  (TK * PITCH)     // 9216 per hi/lo buffer

#define SM_K  0                // K hi @0, lo @KBUF
#define SM_V  (2 * KBUF)       // V hi, lo
#define SM_TOTAL (4 * KBUF)    // 36864 B
#define RED_PITCH 72           // fp32 reduction pitch; 128*72*4 = 36864 (aliases all)

#define LOG2E 1.4426950408889634f

__device__ __forceinline__ uint32_t smem_u32(const void* p) {
    uint32_t a;
    asm("{ .reg .u64 t; cvta.to.shared.u64 t, %1; cvt.u32.u64 %0, t; }" : "=r"(a) : "l"(p));
    return a;
}
#define LDMX4(r, a) \
    asm volatile("ldmatrix.sync.aligned.m8n8.x4.shared.b16 {%0,%1,%2,%3}, [%4];" \
        : "=r"((r)[0]), "=r"((r)[1]), "=r"((r)[2]), "=r"((r)[3]) : "r"(a))
#define LDMX4T(r, a) \
    asm volatile("ldmatrix.sync.aligned.m8n8.x4.trans.shared.b16 {%0,%1,%2,%3}, [%4];" \
        : "=r"((r)[0]), "=r"((r)[1]), "=r"((r)[2]), "=r"((r)[3]) : "r"(a))
#define MMA(c, av, bv) \
    asm volatile("mma.sync.aligned.m16n8k16.row.col.f32.bf16.bf16.f32 " \
        "{%0,%1,%2,%3}, {%4,%5,%6,%7}, {%8,%9}, {%0,%1,%2,%3};" \
        : "+f"((c)[0]), "+f"((c)[1]), "+f"((c)[2]), "+f"((c)[3]) \
        : "r"((av)[0]), "r"((av)[1]), "r"((av)[2]), "r"((av)[3]), \
          "r"((bv)[0]), "r"((bv)[1]))

__device__ __forceinline__ float ex2f(float x) {
    float r;
    asm("ex2.approx.ftz.f32 %0, %1;" : "=f"(r) : "f"(x));
    return r;
}
__device__ __forceinline__ void split_pack(float x, float y, uint32_t& hi, uint32_t& lo) {
    __nv_bfloat16 xh = __float2bfloat16(x), yh = __float2bfloat16(y);
    float xr = x - __bfloat162float(xh);
    float yr = y - __bfloat162float(yh);
    __nv_bfloat16 xl = __float2bfloat16(xr), yl = __float2bfloat16(yr);
    hi = ((uint32_t)__bfloat16_as_ushort(yh) << 16) | (uint32_t)__bfloat16_as_ushort(xh);
    lo = ((uint32_t)__bfloat16_as_ushort(yl) << 16) | (uint32_t)__bfloat16_as_ushort(xl);
}
template<int ROWS>
__device__ __forceinline__ void ldg_tile(const float* __restrict__ g,
                                         float4* r, int tid) {
    #pragma unroll
    for (int i = 0; i < (ROWS * 16) / NTH; ++i) {
        int f = tid + i * NTH;
        int row = f >> 4, d0 = (f & 15) << 2;
        r[i] = *(const float4*)&g[(size_t)row * DD + d0];
    }
}
template<int ROWS>
__device__ __forceinline__ void sts_tile(const float4* r, char* smhi, int bufsz,
                                         int tid, float scale) {
    #pragma unroll
    for (int i = 0; i < (ROWS * 16) / NTH; ++i) {
        int f = tid + i * NTH;
        int row = f >> 4, d0 = (f & 15) << 2;
        uint32_t h0, l0, h1, l1;
        split_pack(r[i].x * scale, r[i].y * scale, h0, l0);
        split_pack(r[i].z * scale, r[i].w * scale, h1, l1);
        int off = row * PITCH + d0 * 2;
        *(uint2*)(smhi + off)         = make_uint2(h0, h1);
        *(uint2*)(smhi + bufsz + off) = make_uint2(l0, l1);
    }
}

__global__ void __launch_bounds__(NTH, 1)
fa_fa10_kernel(const float* __restrict__ q, const float* __restrict__ k,
               const float* __restrict__ v, float* __restrict__ out)
{
    extern __shared__ char smem[];
    const uint32_t sb = smem_u32(smem);
    const int tid  = threadIdx.x;
    const int wid  = tid >> 5;
    const int lane = tid & 31;
    const int m    = wid & 7;    // M-group: rows m*16 .. +15
    const int g    = wid >> 3;   // key-group: keys g*32 .. +31
    const int b  = blockIdx.y;
    const int q0 = blockIdx.x * TQ;

    const float* Qg = q + ((size_t)b * S_LEN + q0) * DD;
    const float* Kg = k + (size_t)b * S_LEN * DD;
    const float* Vg = v + (size_t)b * S_LEN * DD;
    float*       Og = out + ((size_t)b * S_LEN + q0) * DD;

    // ---- prologue: stage Q (x log2e) across K+V regions, grab persistent A-frags ----
    {
        float4 qf[4];
        ldg_tile<TQ>(Qg, qf, tid);
        sts_tile<TQ>(qf, smem, TQ * PITCH, tid, LOG2E);  // hi @0, lo @18432
    }
    __syncthreads();

    uint32_t qhi[4][4], qlo[4][4];
    {
        const uint32_t aQ = sb +
            (uint32_t)((m * 16 + (lane & 15)) * PITCH + (lane >> 4) * 16);
        #pragma unroll
        for (int ks = 0; ks < 4; ++ks) {
            LDMX4(qhi[ks], aQ + ks * 32);
            LDMX4(qlo[ks], aQ + TQ * PITCH + ks * 32);
        }
    }
    __syncthreads();

    // stage K0, V0
    float4 pf[2];
    ldg_tile<TK>(Kg, pf, tid);
    sts_tile<TK>(pf, smem + SM_K, KBUF, tid, 1.0f);
    ldg_tile<TK>(Vg, pf, tid);
    sts_tile<TK>(pf, smem + SM_V, KBUF, tid, 1.0f);
    __syncthreads();

    // per-lane B-operand bases (warp's 32-key slice at rows g*32..)
    const uint32_t bK = sb + SM_K +
        (uint32_t)((g * 32 + ((lane >> 4) & 1) * 8 + (lane & 7)) * PITCH +
                   ((lane >> 3) & 1) * 16);
    const uint32_t bV = sb + SM_V +
        (uint32_t)((g * 32 + ((lane >> 3) & 1) * 8 + (lane & 7)) * PITCH +
                   (((lane >> 4) & 1) * 8) * 2);

    float acc2[8][4];   // O partial: 16 rows x 64 d, over warp's keys
    #pragma unroll
    for (int ni = 0; ni < 8; ++ni)
        #pragma unroll
        for (int e = 0; e < 4; ++e) acc2[ni][e] = 0.0f;

    for (int t = 0; t < NTILES; ++t) {
        const int tn = (t + 1 < NTILES) ? t + 1 : 0;

        // ---- prefetch K(t+1); GEMM1(t): S(16 x 32 per warp) ----
        ldg_tile<TK>(Kg + (size_t)(tn * TK) * DD, pf, tid);

        float acc1[4][4];
        #pragma unroll
        for (int n = 0; n < 4; ++n)
            #pragma unroll
            for (int e = 0; e < 4; ++e) acc1[n][e] = 0.0f;

        #pragma unroll
        for (int ks = 0; ks < 4; ++ks) {
            #pragma unroll
            for (int p = 0; p < 2; ++p) {     // n-pairs within warp's 32 keys
                uint32_t bb = bK + (uint32_t)(p * 16 * PITCH + ks * 32);
                uint32_t bhi[4], blo[4];
                LDMX4(bhi, bb);
                LDMX4(blo, bb + KBUF);
                MMA(acc1[2*p],   qhi[ks], bhi);
                MMA(acc1[2*p],   qhi[ks], blo);
                MMA(acc1[2*p],   qlo[ks], bhi);
                MMA(acc1[2*p+1], qhi[ks], bhi + 2);
                MMA(acc1[2*p+1], qhi[ks], blo + 2);
                MMA(acc1[2*p+1], qlo[ks], bhi + 2);
            }
        }
        __syncthreads();                      // all warps done reading K(t)

        sts_tile<TK>(pf, smem + SM_K, KBUF, tid, 1.0f);   // K(t+1)
        ldg_tile<TK>(Vg + (size_t)(tn * TK) * DD, pf, tid);

        // ---- GEMM2(t): O_partial += P @ V[warp keys], exp fused ----
        #pragma unroll
        for (int ks = 0; ks < 2; ++ks) {      // warp's 32 keys, 16 per step
            uint32_t phi[4], plo[4];
            {
                float e0 = ex2f(acc1[2*ks][0]);
                float e1 = ex2f(acc1[2*ks][1]);
                float e2 = ex2f(acc1[2*ks][2]);
                float e3 = ex2f(acc1[2*ks][3]);
                split_pack(e0, e1, phi[0], plo[0]);
                split_pack(e2, e3, phi[1], plo[1]);
                float f0 = ex2f(acc1[2*ks+1][0]);
                float f1 = ex2f(acc1[2*ks+1][1]);
                float f2 = ex2f(acc1[2*ks+1][2]);
                float f3 = ex2f(acc1[2*ks+1][3]);
                split_pack(f0, f1, phi[2], plo[2]);
                split_pack(f2, f3, phi[3], plo[3]);
            }
            #pragma unroll
            for (int p = 0; p < 4; ++p) {     // d-pairs: blocks 2p, 2p+1
                uint32_t bb = bV + (uint32_t)(ks * 16 * PITCH + p * 32);
                uint32_t bhi[4], blo[4];
                LDMX4T(bhi, bb);
                LDMX4T(blo, bb + KBUF);
                MMA(acc2[2*p],   phi, bhi);
                MMA(acc2[2*p],   phi, blo);
                MMA(acc2[2*p],   plo, bhi);
                MMA(acc2[2*p+1], phi, bhi + 2);
                MMA(acc2[2*p+1], phi, blo + 2);
                MMA(acc2[2*p+1], plo, bhi + 2);
            }
        }
        __syncthreads();                      // all warps done reading V(t)
        sts_tile<TK>(pf, smem + SM_V, KBUF, tid, 1.0f);   // V(t+1)
    }

    // ---- split-K reduction: g==1 -> smem, g==0 adds and stores ----
    __syncthreads();                          // everyone past last V read/write
    float* red = (float*)smem;
    if (g == 1) {
        #pragma unroll
        for (int ni = 0; ni < 8; ++ni) {
            int r = m * 16 + (lane >> 2);
            int c = ni * 8 + (lane & 3) * 2;
            *(float2*)&red[r * RED_PITCH + c] =
                make_float2(acc2[ni][0], acc2[ni][1]);
            *(float2*)&red[(r + 8) * RED_PITCH + c] =
                make_float2(acc2[ni][2], acc2[ni][3]);
        }
    }
    __syncthreads();
    if (g == 0) {
        #pragma unroll
        for (int ni = 0; ni < 8; ++ni) {
            int r = m * 16 + (lane >> 2);
            int c = ni * 8 + (lane & 3) * 2;
            float2 p0 = *(const float2*)&red[r * RED_PITCH + c];
            float2 p1 = *(const float2*)&red[(r + 8) * RED_PITCH + c];
            *(float2*)&Og[(size_t)r * DD + c] =
                make_float2(acc2[ni][0] + p0.x, acc2[ni][1] + p0.y);
            *(float2*)&Og[(size_t)(r + 8) * DD + c] =
                make_float2(acc2[ni][2] + p1.x, acc2[ni][3] + p1.y);
        }
    }
}

extern "C" void kernel_launch(void* const* d_in, const int* in_sizes, int n_in,
                              void* d_out, int out_size)
{
    const float* q = (const float*)d_in[0];
    const float* k = (const float*)d_in[1];
    const float* v = (const float*)d_in[2];
    float* out = (float*)d_out;
    (void)in_sizes; (void)n_in; (void)out_size;

    cudaFuncSetAttribute(fa_fa10_kernel,
                         cudaFuncAttributeMaxDynamicSharedMemorySize, SM_TOTAL);
    dim3 grid(S_LEN / TQ, B_SZ);   // 32 x 4 = 128 CTAs, one wave
    fa_fa10_kernel<<<grid, NTH, SM_TOTAL>>>(q, k, v, out);
}

// round 11
// speedup vs baseline: 1.2488x; 1.1559x over previous
#include <cuda_runtime.h>
#include <cuda_bf16.h>
#include <cstdint>

// out[b,i,:] = sum_j exp(q_i . k_j) * v_j   (B=4, S=4096, D=64, fp32)
// mma.sync bf16 split-precision, FA-style register P.
// R11: R10 + register double-buffered B-fragments (LDSM for step s+1 issued
//      before MMAs of step s) in both GEMMs; packed bf16x2 split.

#define S_LEN 4096
#define B_SZ  4
#define DD    64
#define TQ    128
#define TK    64
#define NTH   512
#define NTILES (S_LEN / TK)

#define PITCH 144              // 64 bf16 + 8B pad
#define KBUF  (TK * PITCH)     // 9216 per hi/lo buffer

#define SM_K  0                // K hi @0, lo @KBUF
#define SM_V  (2 * KBUF)       // V hi, lo
#define SM_TOTAL (4 * KBUF)    // 36864 B
#define RED_PITCH 72           // fp32 reduction pitch; 128*72*4 = 36864

#define LOG2E 1.4426950408889634f

__device__ __forceinline__ uint32_t smem_u32(const void* p) {
    uint32_t a;
    asm("{ .reg .u64 t; cvta.to.shared.u64 t, %1; cvt.u32.u64 %0, t; }" : "=r"(a) : "l"(p));
    return a;
}
#define LDMX4(r, a) \
    asm volatile("ldmatrix.sync.aligned.m8n8.x4.shared.b16 {%0,%1,%2,%3}, [%4];" \
        : "=r"((r)[0]), "=r"((r)[1]), "=r"((r)[2]), "=r"((r)[3]) : "r"(a))
#define LDMX4T(r, a) \
    asm volatile("ldmatrix.sync.aligned.m8n8.x4.trans.shared.b16 {%0,%1,%2,%3}, [%4];" \
        : "=r"((r)[0]), "=r"((r)[1]), "=r"((r)[2]), "=r"((r)[3]) : "r"(a))
#define MMA(c, av, bv) \
    asm volatile("mma.sync.aligned.m16n8k16.row.col.f32.bf16.bf16.f32 " \
        "{%0,%1,%2,%3}, {%4,%5,%6,%7}, {%8,%9}, {%0,%1,%2,%3};" \
        : "+f"((c)[0]), "+f"((c)[1]), "+f"((c)[2]), "+f"((c)[3]) \
        : "r"((av)[0]), "r"((av)[1]), "r"((av)[2]), "r"((av)[3]), \
          "r"((bv)[0]), "r"((bv)[1]))

__device__ __forceinline__ float ex2f(float x) {
    float r;
    asm("ex2.approx.ftz.f32 %0, %1;" : "=f"(r) : "f"(x));
    return r;
}
// x -> low half, y -> high half; hi = bf16x2(x,y), lo = bf16x2 of residuals
__device__ __forceinline__ void split_pack(float x, float y, uint32_t& hi, uint32_t& lo) {
    asm("cvt.rn.bf16x2.f32 %0, %1, %2;" : "=r"(hi) : "f"(y), "f"(x));
    float xh = __uint_as_float(hi << 16);
    float yh = __uint_as_float(hi & 0xffff0000u);
    asm("cvt.rn.bf16x2.f32 %0, %1, %2;" : "=r"(lo) : "f"(y - yh), "f"(x - xh));
}
template<int ROWS>
__device__ __forceinline__ void ldg_tile(const float* __restrict__ g,
                                         float4* r, int tid) {
    #pragma unroll
    for (int i = 0; i < (ROWS * 16) / NTH; ++i) {
        int f = tid + i * NTH;
        int row = f >> 4, d0 = (f & 15) << 2;
        r[i] = *(const float4*)&g[(size_t)row * DD + d0];
    }
}
template<int ROWS>
__device__ __forceinline__ void sts_tile(const float4* r, char* smhi, int bufsz,
                                         int tid, float scale) {
    #pragma unroll
    for (int i = 0; i < (ROWS * 16) / NTH; ++i) {
        int f = tid + i * NTH;
        int row = f >> 4, d0 = (f & 15) << 2;
        uint32_t h0, l0, h1, l1;
        split_pack(r[i].x * scale, r[i].y * scale, h0, l0);
        split_pack(r[i].z * scale, r[i].w * scale, h1, l1);
        int off = row * PITCH + d0 * 2;
        *(uint2*)(smhi + off)         = make_uint2(h0, h1);
        *(uint2*)(smhi + bufsz + off) = make_uint2(l0, l1);
    }
}

__global__ void __launch_bounds__(NTH, 1)
fa_fa11_kernel(const float* __restrict__ q, const float* __restrict__ k,
               const float* __restrict__ v, float* __restrict__ out)
{
    extern __shared__ char smem[];
    const uint32_t sb = smem_u32(smem);
    const int tid  = threadIdx.x;
    const int wid  = tid >> 5;
    const int lane = tid & 31;
    const int m    = wid & 7;    // M-group: rows m*16 .. +15
    const int g    = wid >> 3;   // key-group: keys g*32 .. +31
    const int b  = blockIdx.y;
    const int q0 = blockIdx.x * TQ;

    const float* Qg = q + ((size_t)b * S_LEN + q0) * DD;
    const float* Kg = k + (size_t)b * S_LEN * DD;
    const float* Vg = v + (size_t)b * S_LEN * DD;
    float*       Og = out + ((size_t)b * S_LEN + q0) * DD;

    // ---- prologue: stage Q (x log2e) across K+V regions, grab persistent A-frags ----
    {
        float4 qf[4];
        ldg_tile<TQ>(Qg, qf, tid);
        sts_tile<TQ>(qf, smem, TQ * PITCH, tid, LOG2E);  // hi @0, lo @18432
    }
    __syncthreads();

    uint32_t qhi[4][4], qlo[4][4];
    {
        const uint32_t aQ = sb +
            (uint32_t)((m * 16 + (lane & 15)) * PITCH + (lane >> 4) * 16);
        #pragma unroll
        for (int ks = 0; ks < 4; ++ks) {
            LDMX4(qhi[ks], aQ + ks * 32);
            LDMX4(qlo[ks], aQ + TQ * PITCH + ks * 32);
        }
    }
    __syncthreads();

    // stage K0, V0
    float4 pf[2];
    ldg_tile<TK>(Kg, pf, tid);
    sts_tile<TK>(pf, smem + SM_K, KBUF, tid, 1.0f);
    ldg_tile<TK>(Vg, pf, tid);
    sts_tile<TK>(pf, smem + SM_V, KBUF, tid, 1.0f);
    __syncthreads();

    // per-lane B-operand bases (warp's 32-key slice at rows g*32..)
    const uint32_t bK = sb + SM_K +
        (uint32_t)((g * 32 + ((lane >> 4) & 1) * 8 + (lane & 7)) * PITCH +
                   ((lane >> 3) & 1) * 16);
    const uint32_t bV = sb + SM_V +
        (uint32_t)((g * 32 + ((lane >> 3) & 1) * 8 + (lane & 7)) * PITCH +
                   (((lane >> 4) & 1) * 8) * 2);

    float acc2[8][4];   // O partial: 16 rows x 64 d, over warp's keys
    #pragma unroll
    for (int ni = 0; ni < 8; ++ni)
        #pragma unroll
        for (int e = 0; e < 4; ++e) acc2[ni][e] = 0.0f;

    for (int t = 0; t < NTILES; ++t) {
        const int tn = (t + 1 < NTILES) ? t + 1 : 0;

        // ---- prefetch K(t+1); GEMM1(t): S(16 x 32 per warp) ----
        ldg_tile<TK>(Kg + (size_t)(tn * TK) * DD, pf, tid);

        float acc1[4][4];
        #pragma unroll
        for (int n = 0; n < 4; ++n)
            #pragma unroll
            for (int e = 0; e < 4; ++e) acc1[n][e] = 0.0f;

        {   // 8 steps (ks 0..3) x (p 0..1), B frags double-buffered in regs
            uint32_t Bh[2][4], Bl[2][4];
            LDMX4(Bh[0], bK);
            LDMX4(Bl[0], bK + KBUF);
            #pragma unroll
            for (int s = 0; s < 8; ++s) {
                const int ks = s >> 1, p = s & 1;
                const int cb = s & 1, nb = cb ^ 1;
                if (s < 7) {
                    const int s2 = s + 1;
                    uint32_t bb = bK + (uint32_t)((s2 & 1) * 16 * PITCH + (s2 >> 1) * 32);
                    LDMX4(Bh[nb], bb);
                    LDMX4(Bl[nb], bb + KBUF);
                }
                MMA(acc1[2*p],   qhi[ks], Bh[cb]);
                MMA(acc1[2*p],   qhi[ks], Bl[cb]);
                MMA(acc1[2*p],   qlo[ks], Bh[cb]);
                MMA(acc1[2*p+1], qhi[ks], Bh[cb] + 2);
                MMA(acc1[2*p+1], qhi[ks], Bl[cb] + 2);
                MMA(acc1[2*p+1], qlo[ks], Bh[cb] + 2);
            }
        }
        __syncthreads();                      // all warps done reading K(t)

        sts_tile<TK>(pf, smem + SM_K, KBUF, tid, 1.0f);   // K(t+1)
        ldg_tile<TK>(Vg + (size_t)(tn * TK) * DD, pf, tid);

        // ---- GEMM2(t): 8 steps (k2 0..1) x (p 0..3), V frags double-buffered ----
        {
            uint32_t Vh[2][4], Vl[2][4];
            LDMX4T(Vh[0], bV);
            LDMX4T(Vl[0], bV + KBUF);
            uint32_t phi[4], plo[4];
            #pragma unroll
            for (int s = 0; s < 8; ++s) {
                const int k2 = s >> 2, p = s & 3;
                const int cb = s & 1, nb = cb ^ 1;
                if (p == 0) {   // exp+split for this 16-key group
                    float e0 = ex2f(acc1[2*k2][0]);
                    float e1 = ex2f(acc1[2*k2][1]);
                    float e2 = ex2f(acc1[2*k2][2]);
                    float e3 = ex2f(acc1[2*k2][3]);
                    split_pack(e0, e1, phi[0], plo[0]);
                    split_pack(e2, e3, phi[1], plo[1]);
                    float f0 = ex2f(acc1[2*k2+1][0]);
                    float f1 = ex2f(acc1[2*k2+1][1]);
                    float f2 = ex2f(acc1[2*k2+1][2]);
                    float f3 = ex2f(acc1[2*k2+1][3]);
                    split_pack(f0, f1, phi[2], plo[2]);
                    split_pack(f2, f3, phi[3], plo[3]);
                }
                if (s < 7) {
                    const int s2 = s + 1;
                    uint32_t bb = bV + (uint32_t)((s2 >> 2) * 16 * PITCH + (s2 & 3) * 32);
                    LDMX4T(Vh[nb], bb);
                    LDMX4T(Vl[nb], bb + KBUF);
                }
                MMA(acc2[2*p],   phi, Vh[cb]);
                MMA(acc2[2*p],   phi, Vl[cb]);
                MMA(acc2[2*p],   plo, Vh[cb]);
                MMA(acc2[2*p+1], phi, Vh[cb] + 2);
                MMA(acc2[2*p+1], phi, Vl[cb] + 2);
                MMA(acc2[2*p+1], plo, Vh[cb] + 2);
            }
        }
        __syncthreads();                      // all warps done reading V(t)
        sts_tile<TK>(pf, smem + SM_V, KBUF, tid, 1.0f);   // V(t+1)
    }

    // ---- split-K reduction: g==1 -> smem, g==0 adds and stores ----
    __syncthreads();
    float* red = (float*)smem;
    if (g == 1) {
        #pragma unroll
        for (int ni = 0; ni < 8; ++ni) {
            int r = m * 16 + (lane >> 2);
            int c = ni * 8 + (lane & 3) * 2;
            *(float2*)&red[r * RED_PITCH + c] =
                make_float2(acc2[ni][0], acc2[ni][1]);
            *(float2*)&red[(r + 8) * RED_PITCH + c] =
                make_float2(acc2[ni][2], acc2[ni][3]);
        }
    }
    __syncthreads();
    if (g == 0) {
        #pragma unroll
        for (int ni = 0; ni < 8; ++ni) {
            int r = m * 16 + (lane >> 2);
            int c = ni * 8 + (lane & 3) * 2;
            float2 p0 = *(const float2*)&red[r * RED_PITCH + c];
            float2 p1 = *(const float2*)&red[(r + 8) * RED_PITCH + c];
            *(float2*)&Og[(size_t)r * DD + c] =
                make_float2(acc2[ni][0] + p0.x, acc2[ni][1] + p0.y);
            *(float2*)&Og[(size_t)(r + 8) * DD + c] =
                make_float2(acc2[ni][2] + p1.x, acc2[ni][3] + p1.y);
        }
    }
}

extern "C" void kernel_launch(void* const* d_in, const int* in_sizes, int n_in,
                              void* d_out, int out_size)
{
    const float* q = (const float*)d_in[0];
    const float* k = (const float*)d_in[1];
    const float* v = (const float*)d_in[2];
    float* out = (float*)d_out;
    (void)in_sizes; (void)n_in; (void)out_size;

    cudaFuncSetAttribute(fa_fa11_kernel,
                         cudaFuncAttributeMaxDynamicSharedMemorySize, SM_TOTAL);
    dim3 grid(S_LEN / TQ, B_SZ);   // 32 x 4 = 128 CTAs, one wave
    fa_fa11_kernel<<<grid, NTH, SM_TOTAL>>>(q, k, v, out);
}

// round 12
// speedup vs baseline: 1.2532x; 1.0036x over previous
#include <cuda_runtime.h>
#include <cuda_bf16.h>
#include <cstdint>

// out[b,i,:] = sum_j exp(q_i . k_j) * v_j   (B=4, S=4096, D=64, fp32)
// mma.sync bf16 split-precision, FA-style register P.
// R12: R11 + double-buffered K/V smem -> ONE __syncthreads per tile.

#define S_LEN 4096
#define B_SZ  4
#define DD    64
#define TQ    128
#define TK    64
#define NTH   512
#define NTILES (S_LEN / TK)

#define PITCH 144              // 64 bf16 + 8B pad
#define KBUF  (TK * PITCH)     // 9216 per hi/lo buffer

// K stage s: hi @ s*2*KBUF, lo @ s*2*KBUF + KBUF.   V likewise at SM_V.
#define SM_K  0
#define SM_V  (4 * KBUF)
#define SM_TOTAL (8 * KBUF)    // 73728 B
#define RED_PITCH 72           // fp32 reduction pitch; 128*72*4 = 36864 (aliases)

#define LOG2E 1.4426950408889634f

__device__ __forceinline__ uint32_t smem_u32(const void* p) {
    uint32_t a;
    asm("{ .reg .u64 t; cvta.to.shared.u64 t, %1; cvt.u32.u64 %0, t; }" : "=r"(a) : "l"(p));
    return a;
}
#define LDMX4(r, a) \
    asm volatile("ldmatrix.sync.aligned.m8n8.x4.shared.b16 {%0,%1,%2,%3}, [%4];" \
        : "=r"((r)[0]), "=r"((r)[1]), "=r"((r)[2]), "=r"((r)[3]) : "r"(a))
#define LDMX4T(r, a) \
    asm volatile("ldmatrix.sync.aligned.m8n8.x4.trans.shared.b16 {%0,%1,%2,%3}, [%4];" \
        : "=r"((r)[0]), "=r"((r)[1]), "=r"((r)[2]), "=r"((r)[3]) : "r"(a))
#define MMA(c, av, bv) \
    asm volatile("mma.sync.aligned.m16n8k16.row.col.f32.bf16.bf16.f32 " \
        "{%0,%1,%2,%3}, {%4,%5,%6,%7}, {%8,%9}, {%0,%1,%2,%3};" \
        : "+f"((c)[0]), "+f"((c)[1]), "+f"((c)[2]), "+f"((c)[3]) \
        : "r"((av)[0]), "r"((av)[1]), "r"((av)[2]), "r"((av)[3]), \
          "r"((bv)[0]), "r"((bv)[1]))

__device__ __forceinline__ float ex2f(float x) {
    float r;
    asm("ex2.approx.ftz.f32 %0, %1;" : "=f"(r) : "f"(x));
    return r;
}
// hi = bf16x2(x,y), lo = bf16x2 of residuals
__device__ __forceinline__ void split_pack(float x, float y, uint32_t& hi, uint32_t& lo) {
    asm("cvt.rn.bf16x2.f32 %0, %1, %2;" : "=r"(hi) : "f"(y), "f"(x));
    float xh = __uint_as_float(hi << 16);
    float yh = __uint_as_float(hi & 0xffff0000u);
    asm("cvt.rn.bf16x2.f32 %0, %1, %2;" : "=r"(lo) : "f"(y - yh), "f"(x - xh));
}
template<int ROWS>
__device__ __forceinline__ void ldg_tile(const float* __restrict__ g,
                                         float4* r, int tid) {
    #pragma unroll
    for (int i = 0; i < (ROWS * 16) / NTH; ++i) {
        int f = tid + i * NTH;
        int row = f >> 4, d0 = (f & 15) << 2;
        r[i] = *(const float4*)&g[(size_t)row * DD + d0];
    }
}
template<int ROWS>
__device__ __forceinline__ void sts_tile(const float4* r, char* smhi, int bufsz,
                                         int tid, float scale) {
    #pragma unroll
    for (int i = 0; i < (ROWS * 16) / NTH; ++i) {
        int f = tid + i * NTH;
        int row = f >> 4, d0 = (f & 15) << 2;
        uint32_t h0, l0, h1, l1;
        split_pack(r[i].x * scale, r[i].y * scale, h0, l0);
        split_pack(r[i].z * scale, r[i].w * scale, h1, l1);
        int off = row * PITCH + d0 * 2;
        *(uint2*)(smhi + off)         = make_uint2(h0, h1);
        *(uint2*)(smhi + bufsz + off) = make_uint2(l0, l1);
    }
}

__global__ void __launch_bounds__(NTH, 1)
fa_fa12_kernel(const float* __restrict__ q, const float* __restrict__ k,
               const float* __restrict__ v, float* __restrict__ out)
{
    extern __shared__ char smem[];
    const uint32_t sb = smem_u32(smem);
    const int tid  = threadIdx.x;
    const int wid  = tid >> 5;
    const int lane = tid & 31;
    const int m    = wid & 7;    // M-group: rows m*16 .. +15
    const int g    = wid >> 3;   // key-group: keys g*32 .. +31
    const int b  = blockIdx.y;
    const int q0 = blockIdx.x * TQ;

    const float* Qg = q + ((size_t)b * S_LEN + q0) * DD;
    const float* Kg = k + (size_t)b * S_LEN * DD;
    const float* Vg = v + (size_t)b * S_LEN * DD;
    float*       Og = out + ((size_t)b * S_LEN + q0) * DD;

    // ---- prologue: stage Q (x log2e) into smem[0..36864), grab persistent A-frags ----
    {
        float4 qf[4];
        ldg_tile<TQ>(Qg, qf, tid);
        sts_tile<TQ>(qf, smem, TQ * PITCH, tid, LOG2E);
    }
    __syncthreads();

    uint32_t qhi[4][4], qlo[4][4];
    {
        const uint32_t aQ = sb +
            (uint32_t)((m * 16 + (lane & 15)) * PITCH + (lane >> 4) * 16);
        #pragma unroll
        for (int ks = 0; ks < 4; ++ks) {
            LDMX4(qhi[ks], aQ + ks * 32);
            LDMX4(qlo[ks], aQ + TQ * PITCH + ks * 32);
        }
    }
    __syncthreads();

    // stage K0, V0 into stage-0 buffers
    float4 pf[2];
    ldg_tile<TK>(Kg, pf, tid);
    sts_tile<TK>(pf, smem + SM_K, KBUF, tid, 1.0f);
    ldg_tile<TK>(Vg, pf, tid);
    sts_tile<TK>(pf, smem + SM_V, KBUF, tid, 1.0f);
    __syncthreads();

    // per-lane B-operand bases within a stage (add stage offset at use)
    const uint32_t bK = sb + SM_K +
        (uint32_t)((g * 32 + ((lane >> 4) & 1) * 8 + (lane & 7)) * PITCH +
                   ((lane >> 3) & 1) * 16);
    const uint32_t bV = sb + SM_V +
        (uint32_t)((g * 32 + ((lane >> 3) & 1) * 8 + (lane & 7)) * PITCH +
                   (((lane >> 4) & 1) * 8) * 2);

    float acc2[8][4];   // O partial: 16 rows x 64 d, over warp's keys
    #pragma unroll
    for (int ni = 0; ni < 8; ++ni)
        #pragma unroll
        for (int e = 0; e < 4; ++e) acc2[ni][e] = 0.0f;

    for (int t = 0; t < NTILES; ++t) {
        const int tn = (t + 1 < NTILES) ? t + 1 : 0;
        const uint32_t cur = (uint32_t)((t & 1) * 2 * KBUF);
        const uint32_t nxt = (uint32_t)(((t + 1) & 1) * 2 * KBUF);

        // ---- prefetch K(t+1); GEMM1(t) on K[cur] ----
        ldg_tile<TK>(Kg + (size_t)(tn * TK) * DD, pf, tid);

        float acc1[4][4];
        #pragma unroll
        for (int n = 0; n < 4; ++n)
            #pragma unroll
            for (int e = 0; e < 4; ++e) acc1[n][e] = 0.0f;

        {   // 8 steps (ks 0..3) x (p 0..1), B frags double-buffered in regs
            uint32_t Bh[2][4], Bl[2][4];
            LDMX4(Bh[0], bK + cur);
            LDMX4(Bl[0], bK + cur + KBUF);
            #pragma unroll
            for (int s = 0; s < 8; ++s) {
                const int ks = s >> 1, p = s & 1;
                const int cb = s & 1, nb = cb ^ 1;
                if (s < 7) {
                    const int s2 = s + 1;
                    uint32_t bb = bK + cur +
                        (uint32_t)((s2 & 1) * 16 * PITCH + (s2 >> 1) * 32);
                    LDMX4(Bh[nb], bb);
                    LDMX4(Bl[nb], bb + KBUF);
                }
                MMA(acc1[2*p],   qhi[ks], Bh[cb]);
                MMA(acc1[2*p],   qhi[ks], Bl[cb]);
                MMA(acc1[2*p],   qlo[ks], Bh[cb]);
                MMA(acc1[2*p+1], qhi[ks], Bh[cb] + 2);
                MMA(acc1[2*p+1], qhi[ks], Bl[cb] + 2);
                MMA(acc1[2*p+1], qlo[ks], Bh[cb] + 2);
            }
        }

        // K(t+1) -> other stage (its readers finished before last tile's barrier)
        sts_tile<TK>(pf, smem + SM_K + nxt, KBUF, tid, 1.0f);
        ldg_tile<TK>(Vg + (size_t)(tn * TK) * DD, pf, tid);

        // ---- GEMM2(t) on V[cur]: 8 steps, V frags double-buffered ----
        {
            uint32_t Vh[2][4], Vl[2][4];
            LDMX4T(Vh[0], bV + cur);
            LDMX4T(Vl[0], bV + cur + KBUF);
            uint32_t phi[4], plo[4];
            #pragma unroll
            for (int s = 0; s < 8; ++s) {
                const int k2 = s >> 2, p = s & 3;
                const int cb = s & 1, nb = cb ^ 1;
                if (p == 0) {   // exp+split for this 16-key group
                    float e0 = ex2f(acc1[2*k2][0]);
                    float e1 = ex2f(acc1[2*k2][1]);
                    float e2 = ex2f(acc1[2*k2][2]);
                    float e3 = ex2f(acc1[2*k2][3]);
                    split_pack(e0, e1, phi[0], plo[0]);
                    split_pack(e2, e3, phi[1], plo[1]);
                    float f0 = ex2f(acc1[2*k2+1][0]);
                    float f1 = ex2f(acc1[2*k2+1][1]);
                    float f2 = ex2f(acc1[2*k2+1][2]);
                    float f3 = ex2f(acc1[2*k2+1][3]);
                    split_pack(f0, f1, phi[2], plo[2]);
                    split_pack(f2, f3, phi[3], plo[3]);
                }
                if (s < 7) {
                    const int s2 = s + 1;
                    uint32_t bb = bV + cur +
                        (uint32_t)((s2 >> 2) * 16 * PITCH + (s2 & 3) * 32);
                    LDMX4T(Vh[nb], bb);
                    LDMX4T(Vl[nb], bb + KBUF);
                }
                MMA(acc2[2*p],   phi, Vh[cb]);
                MMA(acc2[2*p],   phi, Vl[cb]);
                MMA(acc2[2*p],   plo, Vh[cb]);
                MMA(acc2[2*p+1], phi, Vh[cb] + 2);
                MMA(acc2[2*p+1], phi, Vl[cb] + 2);
                MMA(acc2[2*p+1], plo, Vh[cb] + 2);
            }
        }

        sts_tile<TK>(pf, smem + SM_V + nxt, KBUF, tid, 1.0f);  // V(t+1)
        __syncthreads();   // single barrier: stage nxt visible; cur reads done
    }

    // ---- split-K reduction: g==1 -> smem, g==0 adds and stores ----
    float* red = (float*)smem;
    if (g == 1) {
        #pragma unroll
        for (int ni = 0; ni < 8; ++ni) {
            int r = m * 16 + (lane >> 2);
            int c = ni * 8 + (lane & 3) * 2;
            *(float2*)&red[r * RED_PITCH + c] =
                make_float2(acc2[ni][0], acc2[ni][1]);
            *(float2*)&red[(r + 8) * RED_PITCH + c] =
                make_float2(acc2[ni][2], acc2[ni][3]);
        }
    }
    __syncthreads();
    if (g == 0) {
        #pragma unroll
        for (int ni = 0; ni < 8; ++ni) {
            int r = m * 16 + (lane >> 2);
            int c = ni * 8 + (lane & 3) * 2;
            float2 p0 = *(const float2*)&red[r * RED_PITCH + c];
            float2 p1 = *(const float2*)&red[(r + 8) * RED_PITCH + c];
            *(float2*)&Og[(size_t)r * DD + c] =
                make_float2(acc2[ni][0] + p0.x, acc2[ni][1] + p0.y);
            *(float2*)&Og[(size_t)(r + 8) * DD + c] =
                make_float2(acc2[ni][2] + p1.x, acc2[ni][3] + p1.y);
        }
    }
}

extern "C" void kernel_launch(void* const* d_in, const int* in_sizes, int n_in,
                              void* d_out, int out_size)
{
    const float* q = (const float*)d_in[0];
    const float* k = (const float*)d_in[1];
    const float* v = (const float*)d_in[2];
    float* out = (float*)d_out;
    (void)in_sizes; (void)n_in; (void)out_size;

    cudaFuncSetAttribute(fa_fa12_kernel,
                         cudaFuncAttributeMaxDynamicSharedMemorySize, SM_TOTAL);
    dim3 grid(S_LEN / TQ, B_SZ);   // 32 x 4 = 128 CTAs, one wave
    fa_fa12_kernel<<<grid, NTH, SM_TOTAL>>>(q, k, v, out);
}